// round 9
// baseline (speedup 1.0000x reference)
#include <cuda_runtime.h>
#include <cuda_fp16.h>
#include <cstdint>
#include <cstddef>

// out = relu(x[131072,256] @ W[256,256]^T + b[256]), fp32 in/out.
// fp16 mma.m16n8k16. CTA 64x256, warp tile 32x64, 8 warps, 2 CTAs/SM.
// KC=32 deep pipeline: 4-buffer B ring (cp.async, up to 2 chunks in flight),
// 2-buffer A ring with distance-2 LDG register prefetch (8 staging regs,
// short liveness). ~110 regs -> ptxas scheduling headroom.

#define DEVI __device__ __forceinline__

static constexpr int M_TOTAL = 131072;
static constexpr int N = 256;
static constexpr int K = 256;
static constexpr int BM = 64;
static constexpr int KC = 32;
static constexpr int KTILES = K / KC;            // 8
static constexpr int STRB = 80;                  // row stride bytes (32h + 8h pad)
static constexpr int A_STAGE = BM * STRB;        // 5120
static constexpr int B_STAGE = N * STRB;         // 20480
static constexpr int A_BASE = 1024;              // [0,1024) bias
static constexpr int B_BASE = A_BASE + 2 * A_STAGE;          // 11264
static constexpr int SMEM_TOTAL = B_BASE + 4 * B_STAGE;      // 93184

__device__ __half g_wh[N * K];

DEVI uint32_t smem_u32(const void* p) {
    uint32_t a;
    asm("{ .reg .u64 t; cvta.to.shared.u64 t, %1; cvt.u32.u64 %0, t; }"
        : "=r"(a) : "l"(p));
    return a;
}

DEVI void cp16(uint32_t dst, const void* src) {
    asm volatile("cp.async.cg.shared.global [%0], [%1], 16;"
                 :: "r"(dst), "l"(__cvta_generic_to_global(src)) : "memory");
}

template <int Npend> DEVI void cp_wait() {
    asm volatile("cp.async.wait_group %0;" :: "n"(Npend) : "memory");
}

DEVI uint32_t pack_h2(float lo, float hi) {
    uint32_t r;
    asm("cvt.rn.f16x2.f32 %0, %1, %2;" : "=r"(r) : "f"(hi), "f"(lo));
    return r;
}

DEVI void ldm_x4(uint32_t* r, uint32_t addr) {
    asm volatile("ldmatrix.sync.aligned.m8n8.x4.shared.b16 {%0,%1,%2,%3}, [%4];"
                 : "=r"(r[0]), "=r"(r[1]), "=r"(r[2]), "=r"(r[3]) : "r"(addr));
}

DEVI void mma_f16(float* c, const uint32_t* a, const uint32_t* b) {
    asm volatile(
        "mma.sync.aligned.m16n8k16.row.col.f32.f16.f16.f32 "
        "{%0,%1,%2,%3}, {%4,%5,%6,%7}, {%8,%9}, {%0,%1,%2,%3};"
        : "+f"(c[0]), "+f"(c[1]), "+f"(c[2]), "+f"(c[3])
        : "r"(a[0]), "r"(a[1]), "r"(a[2]), "r"(a[3]), "r"(b[0]), "r"(b[1]));
}

__global__ void convert_w_kernel(const float* __restrict__ W) {
    int idx4 = (blockIdx.x * 256 + threadIdx.x) * 4;
    float4 v = *reinterpret_cast<const float4*>(W + idx4);
    uint2 h;
    h.x = pack_h2(v.x, v.y);
    h.y = pack_h2(v.z, v.w);
    *reinterpret_cast<uint2*>(g_wh + idx4) = h;
}

__global__ void __launch_bounds__(256, 2)
gemm_f16_kernel(const float* __restrict__ x,
                const float* __restrict__ bias,
                float* __restrict__ out) {
    extern __shared__ char smem[];
    float* sbias = reinterpret_cast<float*>(smem);
    const uint32_t sbase = smem_u32(smem);
    const int tid  = threadIdx.x;
    const int lane = tid & 31;
    const int wid  = tid >> 5;
    const int warp_m = wid >> 2;       // 0..1
    const int warp_n = wid & 3;        // 0..3
    const int gid = lane >> 2;
    const int tg  = lane & 3;

    const int m_base = blockIdx.x * BM;

    sbias[tid] = bias[tid];

    const uint32_t aOff = (uint32_t)((warp_m * 32 + (lane & 15)) * STRB
                                     + (lane >> 4) * 16);
    const uint32_t bOff = (uint32_t)((warp_n * 64 + (lane & 7) + ((lane >> 4) << 3)) * STRB
                                     + ((lane >> 3) & 1) * 16);

    float acc[2][8][4];
    #pragma unroll
    for (int mt = 0; mt < 2; ++mt)
        #pragma unroll
        for (int nt = 0; nt < 8; ++nt)
            #pragma unroll
            for (int j = 0; j < 4; ++j)
                acc[mt][nt][j] = 0.0f;

    auto load_B = [&](int kt) {        // 256x32h chunk -> buf kt&3, one group
        const __half* srcB = g_wh + kt * KC;
        uint32_t dB = sbase + B_BASE + (kt & 3) * B_STAGE;
        #pragma unroll
        for (int i = 0; i < 4; ++i) {
            int g = tid + i * 256;
            int r = g >> 2, c = g & 3;
            cp16(dB + r * STRB + c * 16, srcB + (size_t)r * K + c * 8);
        }
        asm volatile("cp.async.commit_group;" ::: "memory");
    };

    auto ldg_A = [&](int kt, float4* pf) {    // 64x32 fp32 -> 8 regs
        const float* srcA = x + (size_t)m_base * K + kt * KC;
        #pragma unroll
        for (int i = 0; i < 2; ++i) {
            int g = tid + i * 256;
            int r = g >> 3, c = g & 7;
            pf[i] = *reinterpret_cast<const float4*>(srcA + (size_t)r * K + c * 4);
        }
    };

    auto sts_A = [&](int kt, const float4* pf) {
        char* dA = smem + A_BASE + (kt & 1) * A_STAGE;
        #pragma unroll
        for (int i = 0; i < 2; ++i) {
            int g = tid + i * 256;
            int r = g >> 3, c = g & 7;
            uint2 h;
            h.x = pack_h2(pf[i].x, pf[i].y);
            h.y = pack_h2(pf[i].z, pf[i].w);
            *reinterpret_cast<uint2*>(dA + r * STRB + c * 8) = h;
        }
    };

    // Prologue: A(0) in smem, A(1) staged in regs, B(0),B(1) in flight
    float4 pf[2][2];
    ldg_A(0, pf[0]);
    ldg_A(1, pf[1]);
    load_B(0);
    load_B(1);
    sts_A(0, pf[0]);

    #pragma unroll 1
    for (int kt = 0; kt < KTILES; ++kt) {
        if (kt + 2 < KTILES) ldg_A(kt + 2, pf[kt & 1]);   // distance-2 LDG

        if (kt == KTILES - 1) cp_wait<0>(); else cp_wait<1>();
        __syncthreads();   // chunk kt ready everywhere; old buffers reusable

        if (kt + 1 < KTILES) sts_A(kt + 1, pf[(kt + 1) & 1]);  // data landed long ago
        if (kt + 2 < KTILES) load_B(kt + 2);

        const uint32_t aBase = sbase + A_BASE + (kt & 1) * A_STAGE + aOff;
        const uint32_t bBase = sbase + B_BASE + (kt & 3) * B_STAGE + bOff;

        #pragma unroll
        for (int ks = 0; ks < 2; ++ks) {       // 2 k16 steps per chunk
            uint32_t a[2][4], b[4][4];
            ldm_x4(a[0], aBase + ks * 32);
            ldm_x4(a[1], aBase + 16 * STRB + ks * 32);
            #pragma unroll
            for (int j = 0; j < 4; ++j)
                ldm_x4(b[j], bBase + (16 * j) * STRB + ks * 32);
            #pragma unroll
            for (int mt = 0; mt < 2; ++mt)
                #pragma unroll
                for (int nt = 0; nt < 8; ++nt)
                    mma_f16(acc[mt][nt], a[mt], &b[nt >> 1][(nt & 1) * 2]);
        }
    }

    // ---- Epilogue: bias + relu; float2 stores ----
    #pragma unroll
    for (int mt = 0; mt < 2; ++mt) {
        int r0 = m_base + warp_m * 32 + mt * 16 + gid;
        float* o0 = out + (size_t)r0 * N;
        float* o1 = out + (size_t)(r0 + 8) * N;
        #pragma unroll
        for (int nt = 0; nt < 8; ++nt) {
            int c = warp_n * 64 + nt * 8 + 2 * tg;
            float b0 = sbias[c], b1 = sbias[c + 1];
            float2 v0, v1;
            v0.x = fmaxf(acc[mt][nt][0] + b0, 0.0f);
            v0.y = fmaxf(acc[mt][nt][1] + b1, 0.0f);
            v1.x = fmaxf(acc[mt][nt][2] + b0, 0.0f);
            v1.y = fmaxf(acc[mt][nt][3] + b1, 0.0f);
            *reinterpret_cast<float2*>(o0 + c) = v0;
            *reinterpret_cast<float2*>(o1 + c) = v1;
        }
    }
}

extern "C" void kernel_launch(void* const* d_in, const int* in_sizes, int n_in,
                              void* d_out, int out_size) {
    const float* x = (const float*)d_in[0];
    const float* W = (const float*)d_in[1];
    const float* b = (const float*)d_in[2];
    float* out = (float*)d_out;

    convert_w_kernel<<<64, 256>>>(W);

    cudaFuncSetAttribute(gemm_f16_kernel,
                         cudaFuncAttributeMaxDynamicSharedMemorySize, SMEM_TOTAL);
    gemm_f16_kernel<<<M_TOTAL / BM, 256, SMEM_TOTAL>>>(x, b, out);
}

// round 10
// speedup vs baseline: 1.3791x; 1.3791x over previous
#include <cuda_runtime.h>
#include <cuda_fp16.h>
#include <cstdint>
#include <cstddef>

// out = relu(x[131072,256] @ W[256,256]^T + b[256]), fp32 in/out.
// fp16 mma.m16n8k16. CTA 64x256, warp tile 32x64, 8 warps, 2 CTAs/SM, KC=64.
// R7 skeleton + fine-grained schedule: B frags split b01/b23 with staggered
// ldmatrix, A staging split in 8-reg halves, kt loop fully unrolled.

#define DEVI __device__ __forceinline__

static constexpr int M_TOTAL = 131072;
static constexpr int N = 256;
static constexpr int K = 256;
static constexpr int BM = 64;
static constexpr int KC = 64;
static constexpr int KTILES = K / KC;            // 4
static constexpr int STRB = 144;                 // smem row stride bytes
static constexpr int A_STAGE = BM * STRB;        // 9216
static constexpr int B_STAGE = N * STRB;         // 36864
static constexpr int A_BASE = 1024;
static constexpr int SMEM_TOTAL = A_BASE + 2 * (A_STAGE + B_STAGE);  // 93184

__device__ __half g_wh[N * K];

DEVI uint32_t smem_u32(const void* p) {
    uint32_t a;
    asm("{ .reg .u64 t; cvta.to.shared.u64 t, %1; cvt.u32.u64 %0, t; }"
        : "=r"(a) : "l"(p));
    return a;
}

DEVI void cp16(uint32_t dst, const void* src) {
    asm volatile("cp.async.cg.shared.global [%0], [%1], 16;"
                 :: "r"(dst), "l"(__cvta_generic_to_global(src)) : "memory");
}

DEVI uint32_t pack_h2(float lo, float hi) {
    uint32_t r;
    asm("cvt.rn.f16x2.f32 %0, %1, %2;" : "=r"(r) : "f"(hi), "f"(lo));
    return r;
}

DEVI void ldm_x4(uint32_t* r, uint32_t addr) {
    asm volatile("ldmatrix.sync.aligned.m8n8.x4.shared.b16 {%0,%1,%2,%3}, [%4];"
                 : "=r"(r[0]), "=r"(r[1]), "=r"(r[2]), "=r"(r[3]) : "r"(addr));
}

DEVI void mma_f16(float* c, const uint32_t* a, const uint32_t* b) {
    asm volatile(
        "mma.sync.aligned.m16n8k16.row.col.f32.f16.f16.f32 "
        "{%0,%1,%2,%3}, {%4,%5,%6,%7}, {%8,%9}, {%0,%1,%2,%3};"
        : "+f"(c[0]), "+f"(c[1]), "+f"(c[2]), "+f"(c[3])
        : "r"(a[0]), "r"(a[1]), "r"(a[2]), "r"(a[3]), "r"(b[0]), "r"(b[1]));
}

__global__ void convert_w_kernel(const float* __restrict__ W) {
    int idx4 = (blockIdx.x * 256 + threadIdx.x) * 4;
    float4 v = *reinterpret_cast<const float4*>(W + idx4);
    uint2 h;
    h.x = pack_h2(v.x, v.y);
    h.y = pack_h2(v.z, v.w);
    *reinterpret_cast<uint2*>(g_wh + idx4) = h;
}

__global__ void __launch_bounds__(256, 2)
gemm_f16_kernel(const float* __restrict__ x,
                const float* __restrict__ bias,
                float* __restrict__ out) {
    extern __shared__ char smem[];
    float* sbias = reinterpret_cast<float*>(smem);
    const uint32_t sbase = smem_u32(smem);
    const int tid  = threadIdx.x;
    const int lane = tid & 31;
    const int wid  = tid >> 5;
    const int warp_m = wid >> 2;
    const int warp_n = wid & 3;
    const int gid = lane >> 2;
    const int tg  = lane & 3;

    const int m_base = blockIdx.x * BM;

    sbias[tid] = bias[tid];

    const uint32_t aOff = (uint32_t)((warp_m * 32 + (lane & 15)) * STRB
                                     + ((lane >> 4) * 8) * 2);
    const uint32_t bOff = (uint32_t)((warp_n * 64 + (lane & 7) + ((lane >> 4) << 3)) * STRB
                                     + (((lane >> 3) & 1) * 8) * 2);

    float acc[2][8][4];
    #pragma unroll
    for (int mt = 0; mt < 2; ++mt)
        #pragma unroll
        for (int nt = 0; nt < 8; ++nt)
            #pragma unroll
            for (int j = 0; j < 4; ++j)
                acc[mt][nt][j] = 0.0f;

    const int ar = tid >> 4;           // A granule row (16 granules/row)
    const int ac = tid & 15;
    const int br = tid >> 3;
    const int bc = tid & 7;

    auto load_B = [&](int kt) {
        const __half* srcB = g_wh + kt * KC;
        uint32_t dB = sbase + A_BASE + 2 * A_STAGE + (kt & 1) * B_STAGE;
        #pragma unroll
        for (int i = 0; i < 8; ++i) {
            int r = br + i * 32;
            cp16(dB + r * STRB + bc * 16, srcB + (size_t)r * K + bc * 8);
        }
        asm volatile("cp.async.commit_group;" ::: "memory");
    };

    // A chunk split into two halves of 8 regs (2 float4) each
    auto ldg_half = [&](int kt, int h, float4* pf) {
        const float* srcA = x + (size_t)m_base * K + kt * KC;
        #pragma unroll
        for (int i = 0; i < 2; ++i) {
            int r = ar + (2 * h + i) * 16;
            pf[i] = *reinterpret_cast<const float4*>(srcA + (size_t)r * K + ac * 4);
        }
    };
    auto sts_half = [&](int kt, int h, const float4* pf) {
        char* dA = smem + A_BASE + (kt & 1) * A_STAGE;
        #pragma unroll
        for (int i = 0; i < 2; ++i) {
            int r = ar + (2 * h + i) * 16;
            uint2 hh;
            hh.x = pack_h2(pf[i].x, pf[i].y);
            hh.y = pack_h2(pf[i].z, pf[i].w);
            *reinterpret_cast<uint2*>(dA + r * STRB + ac * 8) = hh;
        }
    };

    // ---- Prologue: chunk 0 staged, B(0) in flight ----
    {
        float4 p0[2], p1[2];
        ldg_half(0, 0, p0);
        ldg_half(0, 1, p1);
        load_B(0);
        sts_half(0, 0, p0);
        sts_half(0, 1, p1);
    }

    float4 pfA[2], pfB[2];

    #pragma unroll
    for (int kt = 0; kt < KTILES; ++kt) {
        const bool pre = (kt + 1 < KTILES);
        if (pre) ldg_half(kt + 1, 0, pfA);   // in flight across wait+sync

        asm volatile("cp.async.wait_group 0;" ::: "memory");
        __syncthreads();

        if (pre) load_B(kt + 1);

        const uint32_t aBase = sbase + A_BASE + (kt & 1) * A_STAGE + aOff;
        const uint32_t bBase = sbase + A_BASE + 2 * A_STAGE + (kt & 1) * B_STAGE + bOff;

        uint32_t a[2][2][4];      // [slot][mt]
        uint32_t b01[2][2][4];    // [slot][j]  n-tiles 0..3
        uint32_t b23[2][4];       //           n-tiles 4..7

        ldm_x4(a[0][0], aBase);
        ldm_x4(a[0][1], aBase + 16 * STRB);
        ldm_x4(b01[0][0], bBase);
        ldm_x4(b01[0][1], bBase + 16 * STRB);

        #pragma unroll
        for (int ks = 0; ks < 4; ++ks) {
            const int cur = ks & 1, nxt = cur ^ 1;

            // b23 for this ks: latency hidden behind the b01 half-block below
            ldm_x4(b23[0], bBase + 32 * STRB + ks * 32);
            ldm_x4(b23[1], bBase + 48 * STRB + ks * 32);

            #pragma unroll
            for (int mt = 0; mt < 2; ++mt)
                #pragma unroll
                for (int nt = 0; nt < 4; ++nt)
                    mma_f16(acc[mt][nt], a[cur][mt], &b01[cur][nt >> 1][(nt & 1) * 2]);

            if (ks == 0 && pre) ldg_half(kt + 1, 1, pfB);
            if (ks < 3) {
                ldm_x4(a[nxt][0], aBase + (ks + 1) * 32);
                ldm_x4(a[nxt][1], aBase + 16 * STRB + (ks + 1) * 32);
                ldm_x4(b01[nxt][0], bBase + (ks + 1) * 32);
                ldm_x4(b01[nxt][1], bBase + 16 * STRB + (ks + 1) * 32);
            }
            if (ks == 2 && pre) sts_half(kt + 1, 0, pfA);

            #pragma unroll
            for (int mt = 0; mt < 2; ++mt)
                #pragma unroll
                for (int nt = 4; nt < 8; ++nt)
                    mma_f16(acc[mt][nt], a[cur][mt], &b23[(nt >> 1) - 2][(nt & 1) * 2]);

            if (ks == 3 && pre) sts_half(kt + 1, 1, pfB);
        }
    }

    // ---- Epilogue: bias + relu; float2 stores ----
    #pragma unroll
    for (int mt = 0; mt < 2; ++mt) {
        int r0 = m_base + warp_m * 32 + mt * 16 + gid;
        float* o0 = out + (size_t)r0 * N;
        float* o1 = out + (size_t)(r0 + 8) * N;
        #pragma unroll
        for (int nt = 0; nt < 8; ++nt) {
            int c = warp_n * 64 + nt * 8 + 2 * tg;
            float b0 = sbias[c], b1 = sbias[c + 1];
            float2 v0, v1;
            v0.x = fmaxf(acc[mt][nt][0] + b0, 0.0f);
            v0.y = fmaxf(acc[mt][nt][1] + b1, 0.0f);
            v1.x = fmaxf(acc[mt][nt][2] + b0, 0.0f);
            v1.y = fmaxf(acc[mt][nt][3] + b1, 0.0f);
            *reinterpret_cast<float2*>(o0 + c) = v0;
            *reinterpret_cast<float2*>(o1 + c) = v1;
        }
    }
}

extern "C" void kernel_launch(void* const* d_in, const int* in_sizes, int n_in,
                              void* d_out, int out_size) {
    const float* x = (const float*)d_in[0];
    const float* W = (const float*)d_in[1];
    const float* b = (const float*)d_in[2];
    float* out = (float*)d_out;

    convert_w_kernel<<<64, 256>>>(W);

    cudaFuncSetAttribute(gemm_f16_kernel,
                         cudaFuncAttributeMaxDynamicSharedMemorySize, SMEM_TOTAL);
    gemm_f16_kernel<<<M_TOTAL / BM, 256, SMEM_TOTAL>>>(x, b, out);
}